// round 5
// baseline (speedup 1.0000x reference)
#include <cuda_runtime.h>

// Guided_Conv: 4096 independent 24x24x9 patches.
// patch n = b*256 + i*16 + j  (b=batch, i=patch-row, j=patch-col)
//   input  pixel (pr,pc,f): guidance/depth[ ((b*384 + i*24+pr)*384 + j*24+pc)*9 + f ]
//   output pixel (pr,pc,f): out[ n*5184 + (pr*24+pc)*9 + f ]   (contiguous block per patch)

#define NPIX   576            // 24*24
#define THREADS 576
#define ROW_F4 54             // 24*9/4 float4 per patch row
#define ROWSTRIDE4 864        // 384*9/4 float4 per image row

// Channel-planar depth tile with zero halo:
//   plane f: 26x26 single-channel pixels, row stride DROW=40 floats.
//   pixel (pp,qq), pp,qq in [-1,24], at f*DPS + (pp+1)*40 + (qq+1).
// DPS = 1068: %32==12 -> scatter banks (12*ch+qq)%32 have max 2-way conflict
//             %4 ==0 -> window col base 4*bc is 16B-aligned (LDS.128 legal)
#define DROW 40
#define DPS  1068
#define DPLANAR_FLOATS (DPS * 9)

__global__ __launch_bounds__(THREADS, 3)
void guided_conv_kernel(const float* __restrict__ guidance,
                        const float* __restrict__ depth,
                        const float* __restrict__ conv_w,   // (3,3,9,9)
                        const float* __restrict__ conv_b,   // (9,)
                        const float* __restrict__ dense_w,  // (9,81)
                        const float* __restrict__ dense_b,  // (81,)
                        float* __restrict__ out)
{
    __shared__ __align__(16) float g_s[NPIX * 9];            // guidance patch -> dc buffer
    __shared__ __align__(16) float d_planar[DPLANAR_FLOATS]; // planar depth -> output staging
    __shared__ float cw_s[729];                              // conv_w
    __shared__ float dw_s[729];                              // dense_w
    __shared__ float cb_s[9];
    __shared__ float db_s[81];
    __shared__ float c_s[81];                                // conv out [k][o]
    __shared__ float gap_s[9];
    __shared__ float dvec_s[81];                             // dense out [i][o]
    __shared__ float w1_s[81];                               // depthwise kernel [k][f]
    __shared__ float w2_s[81];                               // channel mix [i][o]

    const int n   = blockIdx.x;
    const int b   = n >> 8;
    const int pi  = (n >> 4) & 15;
    const int pj  = n & 15;
    const int tid = threadIdx.x;

    // ---- Phase 1: stage guidance (float4), depth (planar scatter), weights ----
    // Zero only the halo cells of each plane (disjoint from interior writes).
    for (int h = tid; h < 900; h += THREADS) {
        const int f = h / 100;
        const int r = h - f * 100;
        int addr;
        if (r < 26)       addr = r;                        // planar row 0
        else if (r < 52)  addr = 25 * DROW + (r - 26);     // planar row 25
        else if (r < 76)  addr = (r - 52 + 1) * DROW;      // planar col 0
        else              addr = (r - 76 + 1) * DROW + 25; // planar col 25
        d_planar[f * DPS + addr] = 0.f;
    }

    const int base4 = (((b * 384 + pi * 24) * 384 + pj * 24) * 9) >> 2;
    const float4* g4 = reinterpret_cast<const float4*>(guidance);
    const float4* d4 = reinterpret_cast<const float4*>(depth);
    float4* gs4 = reinterpret_cast<float4*>(g_s);

    for (int idx = tid; idx < 24 * ROW_F4; idx += THREADS) {
        const int pr = idx / ROW_F4;
        const int c4 = idx - pr * ROW_F4;
        const int gi = base4 + pr * ROWSTRIDE4 + c4;
        gs4[idx] = g4[gi];
        const float4 dv = d4[gi];
        // scatter 4 floats to channel planes: row float offset t -> (qq=t/9, ch=t%9)
        const int t0 = c4 * 4;
        const float dvs[4] = {dv.x, dv.y, dv.z, dv.w};
        #pragma unroll
        for (int j = 0; j < 4; j++) {
            const int t  = t0 + j;
            const int qq = t / 9;
            const int ch = t - qq * 9;
            d_planar[ch * DPS + (pr + 1) * DROW + (qq + 1)] = dvs[j];
        }
    }
    for (int idx = tid; idx < 729; idx += THREADS) {
        cw_s[idx] = conv_w[idx];
        dw_s[idx] = dense_w[idx];
    }
    if (tid < 81) db_s[tid] = dense_b[tid];
    if (tid >= 96 && tid < 105) cb_s[tid - 96] = conv_b[tid - 96];
    __syncthreads();

    // ---- Phase 2: strided conv (tid<81)  ||  patch mean (warps 3..11) ----
    if (tid < 81) {
        const int o  = tid % 9;
        const int k  = tid / 9;
        const int ky = k / 3, kx = k % 3;
        float acc = cb_s[o];
        #pragma unroll
        for (int r = 0; r < 3; r++) {
            #pragma unroll
            for (int s = 0; s < 3; s++) {
                const float* gp = &g_s[((8 * ky + r) * 24 + 8 * kx + s) * 9];
                const float* wp = &cw_s[((r * 3 + s) * 9) * 9 + o];
                #pragma unroll
                for (int ii = 0; ii < 9; ii++)
                    acc += gp[ii] * wp[ii * 9];
            }
        }
        c_s[k * 9 + o] = acc;
    } else if (tid >= 96 && tid < 384) {
        const int f    = (tid - 96) >> 5;
        const int lane = tid & 31;
        float s = 0.f;
        #pragma unroll
        for (int p = 0; p < 18; p++)
            s += g_s[(lane + 32 * p) * 9 + f];   // lane stride 9 -> conflict-free
        #pragma unroll
        for (int off = 16; off > 0; off >>= 1)
            s += __shfl_down_sync(0xffffffffu, s, off);
        if (lane == 0) gap_s[f] = s * (1.0f / 576.0f);
    }
    __syncthreads();

    // ---- Phase 3: dense (tid<81)  ||  W1 clip-by-norm (tid 96..104) ----
    if (tid < 81) {
        float acc = db_s[tid];
        #pragma unroll
        for (int ii = 0; ii < 9; ii++)
            acc += gap_s[ii] * dw_s[ii * 81 + tid];
        dvec_s[tid] = acc;
    } else if (tid >= 96 && tid < 105) {
        const int o = tid - 96;
        float ss = 0.f;
        #pragma unroll
        for (int k = 0; k < 9; k++) { const float v = c_s[k * 9 + o]; ss += v * v; }
        const float scale = 1.0f / fmaxf(sqrtf(ss), 1.0f);
        #pragma unroll
        for (int k = 0; k < 9; k++) w1_s[k * 9 + o] = c_s[k * 9 + o] * scale;
    }
    __syncthreads();

    // ---- Phase 5a: per-channel depthwise 3x3 (vectorized window loads)
    //      432 threads = 9 ch x (8x6) blocks of 3 rows x 4 cols; 12 outputs each.
    //      || W2 clip-by-norm on idle warp 17 (gates only phase 5b).
    if (tid < 432) {
        const int f   = tid / 48;
        const int blk = tid - f * 48;
        const int br  = blk / 6;            // 3-row block: pixel rows 3br..3br+2
        const int bc  = blk - br * 6;       // 4-col block: pixel cols 4bc..4bc+3
        // window: planar rows 3br..3br+4, planar cols 4bc..4bc+5 (16B-aligned base)
        const float* plane = d_planar + f * DPS + (3 * br) * DROW + 4 * bc;

        float w1f[9];
        #pragma unroll
        for (int k = 0; k < 9; k++) w1f[k] = w1_s[k * 9 + f];  // warp-broadcast

        float win[18];                       // rolling 3 rows x 6 cols
        #pragma unroll
        for (int r = 0; r < 3; r++) {
            const float4 v4 = *reinterpret_cast<const float4*>(plane + r * DROW);
            const float2 v2 = *reinterpret_cast<const float2*>(plane + r * DROW + 4);
            win[r * 6 + 0] = v4.x; win[r * 6 + 1] = v4.y; win[r * 6 + 2] = v4.z;
            win[r * 6 + 3] = v4.w; win[r * 6 + 4] = v2.x; win[r * 6 + 5] = v2.y;
        }

        #pragma unroll
        for (int rp = 0; rp < 3; rp++) {
            #pragma unroll
            for (int cp = 0; cp < 4; cp++) {
                float acc = 0.f;
                #pragma unroll
                for (int dy = 0; dy < 3; dy++)
                    #pragma unroll
                    for (int dx = 0; dx < 3; dx++)
                        acc += w1f[dy * 3 + dx] * win[dy * 6 + cp + dx];
                const int pix = (3 * br + rp) * 24 + 4 * bc + cp;
                g_s[pix * 9 + f] = acc;
            }
            if (rp < 2) {
                #pragma unroll
                for (int i = 0; i < 12; i++) win[i] = win[i + 6];
                const float4 v4 = *reinterpret_cast<const float4*>(plane + (rp + 3) * DROW);
                const float2 v2 = *reinterpret_cast<const float2*>(plane + (rp + 3) * DROW + 4);
                win[12] = v4.x; win[13] = v4.y; win[14] = v4.z;
                win[15] = v4.w; win[16] = v2.x; win[17] = v2.y;
            }
        }
    } else if (tid >= 544 && tid < 553) {
        // W2 clip-by-norm (per output column, over input dim); needs dvec (phase 3)
        const int o = tid - 544;
        float ss = 0.f;
        #pragma unroll
        for (int ii = 0; ii < 9; ii++) { const float v = dvec_s[ii * 9 + o]; ss += v * v; }
        const float scale = 1.0f / fmaxf(sqrtf(ss), 1.0f);
        #pragma unroll
        for (int ii = 0; ii < 9; ii++) w2_s[ii * 9 + o] = dvec_s[ii * 9 + o] * scale;
    }
    __syncthreads();

    // ---- Phase 5b: 9x9 channel mix; stage output into d_planar (dead now) ----
    {
        float dcv[9];
        #pragma unroll
        for (int ii = 0; ii < 9; ii++) dcv[ii] = g_s[tid * 9 + ii];  // conflict-free
        #pragma unroll
        for (int o = 0; o < 9; o++) {
            float acc = 0.f;
            #pragma unroll
            for (int ii = 0; ii < 9; ii++)
                acc += dcv[ii] * w2_s[ii * 9 + o];                   // broadcast
            d_planar[tid * 9 + o] = acc;                             // conflict-free
        }
    }
    __syncthreads();

    // ---- Phase 6: coalesced float4 store of the whole patch ----
    const float4* src = reinterpret_cast<const float4*>(d_planar);
    float4* dst = reinterpret_cast<float4*>(out + (size_t)n * 5184);
    #pragma unroll 3
    for (int idx = tid; idx < 1296; idx += THREADS)
        dst[idx] = src[idx];
}

extern "C" void kernel_launch(void* const* d_in, const int* in_sizes, int n_in,
                              void* d_out, int out_size) {
    const float* guidance = (const float*)d_in[0];
    const float* depth    = (const float*)d_in[1];
    const float* conv_w   = (const float*)d_in[2];
    const float* conv_b   = (const float*)d_in[3];
    const float* dense_w  = (const float*)d_in[4];
    const float* dense_b  = (const float*)d_in[5];
    float* out = (float*)d_out;

    guided_conv_kernel<<<4096, THREADS>>>(guidance, depth, conv_w, conv_b,
                                          dense_w, dense_b, out);
}

// round 6
// speedup vs baseline: 1.0888x; 1.0888x over previous
#include <cuda_runtime.h>

// Guided_Conv: 4096 independent 24x24x9 patches.
// patch n = b*256 + i*16 + j  (b=batch, i=patch-row, j=patch-col)
//   input  pixel (pr,pc,f): guidance/depth[ ((b*384 + i*24+pr)*384 + j*24+pc)*9 + f ]
//   output pixel (pr,pc,f): out[ n*5184 + (pr*24+pc)*9 + f ]   (contiguous block per patch)

#define NPIX   576            // 24*24
#define THREADS 576
#define ROW_F4 54             // 24*9/4 float4 per patch row
#define ROWSTRIDE4 864        // 384*9/4 float4 per image row

// Channel-planar depth tile with zero halo:
//   plane f: 26x26 single-channel pixels, row stride DROW=40 floats.
//   pixel (pp,qq), pp,qq in [-1,24], at f*DPS + (pp+1)*40 + (qq+1).
// DPS = 1068 (%32==12): scatter banks (12*ch+qq)%32 collide at most 2-way
// (enumerated over t=4L, L=0..31). Depthwise loads stay conflict-free:
// within a warp f is fixed, so plane base only shifts all banks uniformly.
#define DROW 40
#define DPS  1068
#define DPLANAR_FLOATS (DPS * 9)

__global__ __launch_bounds__(THREADS, 3)
void guided_conv_kernel(const float* __restrict__ guidance,
                        const float* __restrict__ depth,
                        const float* __restrict__ conv_w,   // (3,3,9,9)
                        const float* __restrict__ conv_b,   // (9,)
                        const float* __restrict__ dense_w,  // (9,81)
                        const float* __restrict__ dense_b,  // (81,)
                        float* __restrict__ out)
{
    __shared__ __align__(16) float g_s[NPIX * 9];            // guidance patch -> dc buffer
    __shared__ __align__(16) float d_planar[DPLANAR_FLOATS]; // planar depth -> output staging
    __shared__ float cw_s[729];                              // conv_w
    __shared__ float dw_s[729];                              // dense_w
    __shared__ float cb_s[9];
    __shared__ float db_s[81];
    __shared__ float c_s[81];                                // conv out [k][o]
    __shared__ float gap_s[9];
    __shared__ float dvec_s[81];                             // dense out [i][o]
    __shared__ float w1_s[81];                               // depthwise kernel [k][f]
    __shared__ float w2_s[81];                               // channel mix [i][o]

    const int n   = blockIdx.x;
    const int b   = n >> 8;
    const int pi  = (n >> 4) & 15;
    const int pj  = n & 15;
    const int tid = threadIdx.x;

    // ---- Phase 1: stage guidance (float4), depth (planar scatter), weights ----
    // Zero only the halo cells of each plane (disjoint from interior writes).
    for (int h = tid; h < 900; h += THREADS) {
        const int f = h / 100;
        const int r = h - f * 100;
        int addr;
        if (r < 26)       addr = r;                        // planar row 0
        else if (r < 52)  addr = 25 * DROW + (r - 26);     // planar row 25
        else if (r < 76)  addr = (r - 52 + 1) * DROW;      // planar col 0
        else              addr = (r - 76 + 1) * DROW + 25; // planar col 25
        d_planar[f * DPS + addr] = 0.f;
    }

    const int base4 = (((b * 384 + pi * 24) * 384 + pj * 24) * 9) >> 2;
    const float4* g4 = reinterpret_cast<const float4*>(guidance);
    const float4* d4 = reinterpret_cast<const float4*>(depth);
    float4* gs4 = reinterpret_cast<float4*>(g_s);

    for (int idx = tid; idx < 24 * ROW_F4; idx += THREADS) {
        const int pr = idx / ROW_F4;
        const int c4 = idx - pr * ROW_F4;
        const int gi = base4 + pr * ROWSTRIDE4 + c4;
        gs4[idx] = g4[gi];
        const float4 dv = d4[gi];
        // scatter 4 floats to channel planes: row float offset t -> (qq=t/9, ch=t%9)
        const int t0 = c4 * 4;
        const float dvs[4] = {dv.x, dv.y, dv.z, dv.w};
        #pragma unroll
        for (int j = 0; j < 4; j++) {
            const int t  = t0 + j;
            const int qq = t / 9;
            const int ch = t - qq * 9;
            d_planar[ch * DPS + (pr + 1) * DROW + (qq + 1)] = dvs[j];
        }
    }
    for (int idx = tid; idx < 729; idx += THREADS) {
        cw_s[idx] = conv_w[idx];
        dw_s[idx] = dense_w[idx];
    }
    if (tid < 81) db_s[tid] = dense_b[tid];
    if (tid >= 96 && tid < 105) cb_s[tid - 96] = conv_b[tid - 96];
    __syncthreads();

    // ---- Phase 2: strided conv (tid<81)  ||  patch mean (warps 3..11) ----
    if (tid < 81) {
        const int o  = tid % 9;
        const int k  = tid / 9;
        const int ky = k / 3, kx = k % 3;
        float acc = cb_s[o];
        #pragma unroll
        for (int r = 0; r < 3; r++) {
            #pragma unroll
            for (int s = 0; s < 3; s++) {
                const float* gp = &g_s[((8 * ky + r) * 24 + 8 * kx + s) * 9];
                const float* wp = &cw_s[((r * 3 + s) * 9) * 9 + o];
                #pragma unroll
                for (int ii = 0; ii < 9; ii++)
                    acc += gp[ii] * wp[ii * 9];
            }
        }
        c_s[k * 9 + o] = acc;
    } else if (tid >= 96 && tid < 384) {
        const int f    = (tid - 96) >> 5;
        const int lane = tid & 31;
        float s = 0.f;
        #pragma unroll
        for (int p = 0; p < 18; p++)
            s += g_s[(lane + 32 * p) * 9 + f];   // lane stride 9 -> conflict-free
        #pragma unroll
        for (int off = 16; off > 0; off >>= 1)
            s += __shfl_down_sync(0xffffffffu, s, off);
        if (lane == 0) gap_s[f] = s * (1.0f / 576.0f);
    }
    __syncthreads();

    // ---- Phase 3: dense (tid<81)  ||  W1 clip-by-norm (tid 96..104) ----
    if (tid < 81) {
        float acc = db_s[tid];
        #pragma unroll
        for (int ii = 0; ii < 9; ii++)
            acc += gap_s[ii] * dw_s[ii * 81 + tid];
        dvec_s[tid] = acc;
    } else if (tid >= 96 && tid < 105) {
        const int o = tid - 96;
        float ss = 0.f;
        #pragma unroll
        for (int k = 0; k < 9; k++) { const float v = c_s[k * 9 + o]; ss += v * v; }
        const float scale = 1.0f / fmaxf(sqrtf(ss), 1.0f);
        #pragma unroll
        for (int k = 0; k < 9; k++) w1_s[k * 9 + o] = c_s[k * 9 + o] * scale;
    }
    __syncthreads();

    // ---- Phase 5a: per-channel depthwise 3x3.  thread = (channel f, 3x3 block)
    //      W2 clip-by-norm folded into the prologue on 9 lanes of warp 0
    //      (dvec ready since phase-3 barrier; w2 consumed after 5a barrier).
    {
        if (tid < 9) {
            const int o = tid;
            float ss = 0.f;
            #pragma unroll
            for (int ii = 0; ii < 9; ii++) { const float v = dvec_s[ii * 9 + o]; ss += v * v; }
            const float scale = 1.0f / fmaxf(sqrtf(ss), 1.0f);
            #pragma unroll
            for (int ii = 0; ii < 9; ii++) w2_s[ii * 9 + o] = dvec_s[ii * 9 + o] * scale;
        }

        const int f   = tid >> 6;            // fixed channel per warp
        const int blk = tid & 63;
        const int br  = blk >> 3;
        const int bc  = blk & 7;
        // 5x5 planar window: pixel rows 3br-1..3br+3 = planar rows 3br..3br+4
        const float* plane = d_planar + f * DPS + (3 * br) * DROW + 3 * bc;

        float w1f[9];
        #pragma unroll
        for (int k = 0; k < 9; k++) w1f[k] = w1_s[k * 9 + f];  // warp-broadcast

        float win[15];                        // rolling 3-row x 5-col window
        #pragma unroll
        for (int r = 0; r < 3; r++)
            #pragma unroll
            for (int c = 0; c < 5; c++)
                win[r * 5 + c] = plane[r * DROW + c];

        #pragma unroll
        for (int rp = 0; rp < 3; rp++) {
            #pragma unroll
            for (int cp = 0; cp < 3; cp++) {
                float acc = 0.f;
                #pragma unroll
                for (int dy = 0; dy < 3; dy++)
                    #pragma unroll
                    for (int dx = 0; dx < 3; dx++)
                        acc += w1f[dy * 3 + dx] * win[dy * 5 + cp + dx];
                const int pix = (3 * br + rp) * 24 + 3 * bc + cp;
                g_s[pix * 9 + f] = acc;       // banks (8br+27bc)%32: conflict-free
            }
            if (rp < 2) {
                #pragma unroll
                for (int i = 0; i < 10; i++) win[i] = win[i + 5];
                #pragma unroll
                for (int c = 0; c < 5; c++)
                    win[10 + c] = plane[(rp + 3) * DROW + c];
            }
        }
    }
    __syncthreads();

    // ---- Phase 5b: 9x9 channel mix; stage output into d_planar (dead now) ----
    {
        float dcv[9];
        #pragma unroll
        for (int ii = 0; ii < 9; ii++) dcv[ii] = g_s[tid * 9 + ii];  // conflict-free
        #pragma unroll
        for (int o = 0; o < 9; o++) {
            float acc = 0.f;
            #pragma unroll
            for (int ii = 0; ii < 9; ii++)
                acc += dcv[ii] * w2_s[ii * 9 + o];                   // broadcast
            d_planar[tid * 9 + o] = acc;                             // conflict-free
        }
    }
    __syncthreads();

    // ---- Phase 6: coalesced float4 store of the whole patch ----
    const float4* src = reinterpret_cast<const float4*>(d_planar);
    float4* dst = reinterpret_cast<float4*>(out + (size_t)n * 5184);
    #pragma unroll 3
    for (int idx = tid; idx < 1296; idx += THREADS)
        dst[idx] = src[idx];
}

extern "C" void kernel_launch(void* const* d_in, const int* in_sizes, int n_in,
                              void* d_out, int out_size) {
    const float* guidance = (const float*)d_in[0];
    const float* depth    = (const float*)d_in[1];
    const float* conv_w   = (const float*)d_in[2];
    const float* conv_b   = (const float*)d_in[3];
    const float* dense_w  = (const float*)d_in[4];
    const float* dense_b  = (const float*)d_in[5];
    float* out = (float*)d_out;

    guided_conv_kernel<<<4096, THREADS>>>(guidance, depth, conv_w, conv_b,
                                          dense_w, dense_b, out);
}

// round 7
// speedup vs baseline: 1.2004x; 1.1025x over previous
#include <cuda_runtime.h>
#include <cstdint>

// Guided_Conv: 4096 independent 24x24x9 patches.
// patch n = b*256 + i*16 + j  (b=batch, i=patch-row, j=patch-col)
//   input  pixel (pr,pc,f): guidance/depth[ ((b*384 + i*24+pr)*384 + j*24+pc)*9 + f ]
//   output pixel (pr,pc,f): out[ n*5184 + (pr*24+pc)*9 + f ]   (contiguous block per patch)

#define NPIX   576            // 24*24
#define THREADS 576
#define ROW_F4 54             // 24*9/4 float4 per patch row
#define ROWSTRIDE4 864        // 384*9/4 float4 per image row

// Channel-planar depth tile with zero halo (see R6 analysis):
// DPS = 1068 (%32==12): scatter banks collide at most 2-way; %4==0 keeps rows aligned.
#define DROW 40
#define DPS  1068
#define DPLANAR_FLOATS (DPS * 9)

// packed f32x2 FMA (PTX-only; ptxas never fuses 2x fmaf itself)
#define FMA_F32X2(d, a, b, c) \
    asm("fma.rn.f32x2 %0, %1, %2, %3;" : "=l"(d) : "l"(a), "l"(b), "l"(c))

__global__ __launch_bounds__(THREADS, 3)
void guided_conv_kernel(const float* __restrict__ guidance,
                        const float* __restrict__ depth,
                        const float* __restrict__ conv_w,   // (3,3,9,9)
                        const float* __restrict__ conv_b,   // (9,)
                        const float* __restrict__ dense_w,  // (9,81)
                        const float* __restrict__ dense_b,  // (81,)
                        float* __restrict__ out)
{
    __shared__ __align__(16) float g_s[NPIX * 9];            // guidance patch -> dc buffer
    __shared__ __align__(16) float d_planar[DPLANAR_FLOATS]; // planar depth -> output staging
    __shared__ float cw_s[729];                              // conv_w
    __shared__ float dw_s[729];                              // dense_w
    __shared__ float cb_s[9];
    __shared__ float db_s[81];
    __shared__ float c_s[81];                                // conv out [k][o]
    __shared__ float part_s[243];                            // conv partials [r][k*9+o]
    __shared__ float gap_s[9];
    __shared__ float dvec_s[81];                             // dense out [i][o]
    __shared__ float w1_s[81];                               // depthwise kernel [k][f]
    __shared__ __align__(8) float w2p_s[90];                 // mix, padded pairs [ii][10]

    const int n   = blockIdx.x;
    const int b   = n >> 8;
    const int pi  = (n >> 4) & 15;
    const int pj  = n & 15;
    const int tid = threadIdx.x;

    // ---- Phase 1: stage guidance (float4), depth (planar scatter), weights ----
    for (int h = tid; h < 900; h += THREADS) {               // zero plane halos
        const int f = h / 100;
        const int r = h - f * 100;
        int addr;
        if (r < 26)       addr = r;
        else if (r < 52)  addr = 25 * DROW + (r - 26);
        else if (r < 76)  addr = (r - 52 + 1) * DROW;
        else              addr = (r - 76 + 1) * DROW + 25;
        d_planar[f * DPS + addr] = 0.f;
    }

    const int base4 = (((b * 384 + pi * 24) * 384 + pj * 24) * 9) >> 2;
    const float4* g4 = reinterpret_cast<const float4*>(guidance);
    const float4* d4 = reinterpret_cast<const float4*>(depth);
    float4* gs4 = reinterpret_cast<float4*>(g_s);

    for (int idx = tid; idx < 24 * ROW_F4; idx += THREADS) {
        const int pr = idx / ROW_F4;
        const int c4 = idx - pr * ROW_F4;
        const int gi = base4 + pr * ROWSTRIDE4 + c4;
        gs4[idx] = g4[gi];
        const float4 dv = d4[gi];
        const int t0 = c4 * 4;
        const float dvs[4] = {dv.x, dv.y, dv.z, dv.w};
        #pragma unroll
        for (int j = 0; j < 4; j++) {
            const int t  = t0 + j;
            const int qq = t / 9;
            const int ch = t - qq * 9;
            d_planar[ch * DPS + (pr + 1) * DROW + (qq + 1)] = dvs[j];
        }
    }
    for (int idx = tid; idx < 729; idx += THREADS) {
        cw_s[idx] = conv_w[idx];
        dw_s[idx] = dense_w[idx];
    }
    if (tid < 81) db_s[tid] = dense_b[tid];
    if (tid >= 96 && tid < 105) cb_s[tid - 96] = conv_b[tid - 96];
    if (tid >= 112 && tid < 121) w2p_s[(tid - 112) * 10 + 9] = 0.f;  // pad column
    __syncthreads();

    // ---- Phase 2: two independent weight chains on disjoint warp groups ----
    if (tid < 256) {
        // warps 0-7: conv partials (243 thr) -> sum -> W1 clip-by-norm
        if (tid < 243) {
            const int o  = tid % 9;
            const int k  = (tid / 9) % 9;
            const int r  = tid / 81;            // kernel row handled by this thread
            const int ky = k / 3, kx = k % 3;
            float acc = 0.f;
            #pragma unroll
            for (int s = 0; s < 3; s++) {
                const float* gp = &g_s[((8 * ky + r) * 24 + 8 * kx + s) * 9];
                const float* wp = &cw_s[((r * 3 + s) * 9) * 9 + o];
                #pragma unroll
                for (int ii = 0; ii < 9; ii++)
                    acc += gp[ii] * wp[ii * 9];
            }
            part_s[r * 81 + k * 9 + o] = acc;
        }
        asm volatile("bar.sync 1, 256;" ::: "memory");
        if (tid < 81)
            c_s[tid] = cb_s[tid % 9] + part_s[tid] + part_s[81 + tid] + part_s[162 + tid];
        asm volatile("bar.sync 1, 256;" ::: "memory");
        if (tid < 9) {
            const int o = tid;
            float ss = 0.f;
            #pragma unroll
            for (int k = 0; k < 9; k++) { const float v = c_s[k * 9 + o]; ss += v * v; }
            const float scale = 1.0f / fmaxf(sqrtf(ss), 1.0f);
            #pragma unroll
            for (int k = 0; k < 9; k++) w1_s[k * 9 + o] = c_s[k * 9 + o] * scale;
        }
    } else if (tid < 544) {
        // warps 8-16: patch mean -> dense -> W2 clip-by-norm (paired layout)
        {
            const int f    = (tid - 256) >> 5;
            const int lane = tid & 31;
            float s = 0.f;
            #pragma unroll
            for (int p = 0; p < 18; p++)
                s += g_s[(lane + 32 * p) * 9 + f];   // lane stride 9 -> conflict-free
            #pragma unroll
            for (int off = 16; off > 0; off >>= 1)
                s += __shfl_down_sync(0xffffffffu, s, off);
            if (lane == 0) gap_s[f] = s * (1.0f / 576.0f);
        }
        asm volatile("bar.sync 2, 288;" ::: "memory");
        if (tid < 337) {
            const int j = tid - 256;                 // 81 threads
            float acc = db_s[j];
            #pragma unroll
            for (int ii = 0; ii < 9; ii++)
                acc += gap_s[ii] * dw_s[ii * 81 + j];
            dvec_s[j] = acc;
        }
        asm volatile("bar.sync 2, 288;" ::: "memory");
        if (tid < 265) {
            const int o = tid - 256;                 // 9 threads
            float ss = 0.f;
            #pragma unroll
            for (int ii = 0; ii < 9; ii++) { const float v = dvec_s[ii * 9 + o]; ss += v * v; }
            const float scale = 1.0f / fmaxf(sqrtf(ss), 1.0f);
            #pragma unroll
            for (int ii = 0; ii < 9; ii++) w2p_s[ii * 10 + o] = dvec_s[ii * 9 + o] * scale;
        }
    }
    __syncthreads();

    // ---- Phase 5a: per-channel depthwise 3x3.  thread = (channel f, 3x3 block) ----
    {
        const int f   = tid >> 6;            // fixed channel per warp
        const int blk = tid & 63;
        const int br  = blk >> 3;
        const int bc  = blk & 7;
        const float* plane = d_planar + f * DPS + (3 * br) * DROW + 3 * bc;

        float w1f[9];
        #pragma unroll
        for (int k = 0; k < 9; k++) w1f[k] = w1_s[k * 9 + f];  // warp-broadcast

        float win[15];                        // rolling 3-row x 5-col window
        #pragma unroll
        for (int r = 0; r < 3; r++)
            #pragma unroll
            for (int c = 0; c < 5; c++)
                win[r * 5 + c] = plane[r * DROW + c];

        #pragma unroll
        for (int rp = 0; rp < 3; rp++) {
            #pragma unroll
            for (int cp = 0; cp < 3; cp++) {
                float acc = 0.f;
                #pragma unroll
                for (int dy = 0; dy < 3; dy++)
                    #pragma unroll
                    for (int dx = 0; dx < 3; dx++)
                        acc += w1f[dy * 3 + dx] * win[dy * 5 + cp + dx];
                const int pix = (3 * br + rp) * 24 + 3 * bc + cp;
                g_s[pix * 9 + f] = acc;       // banks (8br+27bc)%32: conflict-free
            }
            if (rp < 2) {
                #pragma unroll
                for (int i = 0; i < 10; i++) win[i] = win[i + 5];
                #pragma unroll
                for (int c = 0; c < 5; c++)
                    win[10 + c] = plane[(rp + 3) * DROW + c];
            }
        }
    }
    __syncthreads();

    // ---- Phase 5b: 9x9 channel mix with packed f32x2 FMAs ----
    //      per thread: 9 dc LDS + 45 LDS.64 (w2 pairs, broadcast) + 45 FFMA2 + 9 STS
    {
        float dcv[9];
        #pragma unroll
        for (int ii = 0; ii < 9; ii++) dcv[ii] = g_s[tid * 9 + ii];  // conflict-free

        uint64_t acc[5];
        #pragma unroll
        for (int j = 0; j < 5; j++) acc[j] = 0ull;

        #pragma unroll
        for (int ii = 0; ii < 9; ii++) {
            uint64_t splat;
            const uint32_t xi = __float_as_uint(dcv[ii]);
            asm("mov.b64 %0, {%1, %1};" : "=l"(splat) : "r"(xi));
            const uint64_t* w2row = reinterpret_cast<const uint64_t*>(&w2p_s[ii * 10]);
            #pragma unroll
            for (int j = 0; j < 5; j++) {
                const uint64_t w2v = w2row[j];       // LDS.64, warp-uniform broadcast
                FMA_F32X2(acc[j], splat, w2v, acc[j]);
            }
        }

        float* stage = &d_planar[tid * 9];           // conflict-free (stride 9)
        #pragma unroll
        for (int j = 0; j < 4; j++) {
            stage[2 * j]     = __uint_as_float((uint32_t)acc[j]);
            stage[2 * j + 1] = __uint_as_float((uint32_t)(acc[j] >> 32));
        }
        stage[8] = __uint_as_float((uint32_t)acc[4]);
    }
    __syncthreads();

    // ---- Phase 6: coalesced float4 store of the whole patch ----
    const float4* src = reinterpret_cast<const float4*>(d_planar);
    float4* dst = reinterpret_cast<float4*>(out + (size_t)n * 5184);
    #pragma unroll 3
    for (int idx = tid; idx < 1296; idx += THREADS)
        dst[idx] = src[idx];
}

extern "C" void kernel_launch(void* const* d_in, const int* in_sizes, int n_in,
                              void* d_out, int out_size) {
    const float* guidance = (const float*)d_in[0];
    const float* depth    = (const float*)d_in[1];
    const float* conv_w   = (const float*)d_in[2];
    const float* conv_b   = (const float*)d_in[3];
    const float* dense_w  = (const float*)d_in[4];
    const float* dense_b  = (const float*)d_in[5];
    float* out = (float*)d_out;

    guided_conv_kernel<<<4096, THREADS>>>(guidance, depth, conv_w, conv_b,
                                          dense_w, dense_b, out);
}

// round 8
// speedup vs baseline: 1.2925x; 1.0767x over previous
#include <cuda_runtime.h>
#include <cstdint>

// Guided_Conv: 4096 independent 24x24x9 patches.
// patch n = b*256 + i*16 + j  (b=batch, i=patch-row, j=patch-col)
//   input  pixel (pr,pc,f): guidance/depth[ ((b*384 + i*24+pr)*384 + j*24+pc)*9 + f ]
//   output pixel (pr,pc,f): out[ n*5184 + (pr*24+pc)*9 + f ]   (contiguous block per patch)

#define NPIX   576            // 24*24
#define THREADS 576
#define ROW_F4 54             // 24*9/4 float4 per patch row
#define ROWSTRIDE4 864        // 384*9/4 float4 per image row

// Padded pixel-major depth tile with zero halo:
//   row slot rp = pixel_row+1 in [0,25], row stride DROWP=248 floats.
//   col slots: interior qq in [0,23] at offset 9*qq; right halo (qq=24) at 216
//   (= 9*24, natural); left halo (qq=-1) wrapped to offset 225.
// 248*3 = 744 == 8 (mod 32)  ->  depthwise-load banks (8*br + 27*bc) mod 32
// are all-distinct per warp (27bc hits every residue mod 8; 8br the cosets).
// 248 % 4 == 0 -> interior rows are float4-aligned for staging.
#define DROWP 248
#define DTILE_FLOATS (DROWP * 26)   // 6448 floats; also >= 5184 for output staging

// packed f32x2 FMA (PTX-only; ptxas never fuses 2x fmaf itself)
#define FMA_F32X2(d, a, b, c) \
    asm("fma.rn.f32x2 %0, %1, %2, %3;" : "=l"(d) : "l"(a), "l"(b), "l"(c))

__global__ __launch_bounds__(THREADS, 3)
void guided_conv_kernel(const float* __restrict__ guidance,
                        const float* __restrict__ depth,
                        const float* __restrict__ conv_w,   // (3,3,9,9)
                        const float* __restrict__ conv_b,   // (9,)
                        const float* __restrict__ dense_w,  // (9,81)
                        const float* __restrict__ dense_b,  // (81,)
                        float* __restrict__ out)
{
    __shared__ __align__(16) float g_s[NPIX * 9];          // guidance patch -> dc buffer
    __shared__ __align__(16) float d_s[DTILE_FLOATS];      // depth tile -> output staging
    __shared__ float cw_s[729];                            // conv_w
    __shared__ float dw_s[729];                            // dense_w
    __shared__ float cb_s[9];
    __shared__ float db_s[81];
    __shared__ float c_s[81];                              // conv out [k][o]
    __shared__ float part_s[243];                          // conv partials [r][k*9+o]
    __shared__ float gap_s[9];
    __shared__ float dvec_s[81];                           // dense out [i][o]
    __shared__ float w1_s[81];                             // depthwise kernel [k][f]
    __shared__ __align__(8) float w2p_s[90];               // mix, padded pairs [ii][10]

    const int n   = blockIdx.x;
    const int b   = n >> 8;
    const int pi  = (n >> 4) & 15;
    const int pj  = n & 15;
    const int tid = threadIdx.x;

    // ---- Phase 1: stage guidance + depth (both float4), zero depth halo ----
    // Halo cells actually read: full rows 0 and 25 (offsets 0..233 each),
    // plus col slots 24,25 (offsets 216..233) of rows 1..24.  900 floats.
    for (int h = tid; h < 900; h += THREADS) {
        int addr;
        if (h < 234)      addr = h;                        // row slot 0
        else if (h < 468) addr = 6200 + (h - 234);         // row slot 25 (248*25)
        else {
            const int z = h - 468;
            addr = DROWP * (z / 18 + 1) + 216 + (z % 18);  // slots 24,25 of rows 1..24
        }
        d_s[addr] = 0.f;
    }

    const int base4 = (((b * 384 + pi * 24) * 384 + pj * 24) * 9) >> 2;
    const float4* g4 = reinterpret_cast<const float4*>(guidance);
    const float4* d4 = reinterpret_cast<const float4*>(depth);
    float4* gs4 = reinterpret_cast<float4*>(g_s);
    float4* ds4 = reinterpret_cast<float4*>(d_s);

    for (int idx = tid; idx < 24 * ROW_F4; idx += THREADS) {
        const int pr = idx / ROW_F4;
        const int c4 = idx - pr * ROW_F4;
        const int gi = base4 + pr * ROWSTRIDE4 + c4;
        gs4[idx] = g4[gi];
        ds4[62 * (pr + 1) + c4] = d4[gi];   // row slot pr+1 (248/4 = 62)
    }
    for (int idx = tid; idx < 729; idx += THREADS) {
        cw_s[idx] = conv_w[idx];
        dw_s[idx] = dense_w[idx];
    }
    if (tid < 81) db_s[tid] = dense_b[tid];
    if (tid >= 96 && tid < 105) cb_s[tid - 96] = conv_b[tid - 96];
    if (tid >= 112 && tid < 121) w2p_s[(tid - 112) * 10 + 9] = 0.f;  // pad column
    __syncthreads();

    // ---- Phase 2: two independent weight chains on disjoint warp groups ----
    if (tid < 256) {
        // warps 0-7: conv partials (243 thr) -> sum -> W1 clip-by-norm
        if (tid < 243) {
            const int o  = tid % 9;
            const int k  = (tid / 9) % 9;
            const int r  = tid / 81;            // kernel row handled by this thread
            const int ky = k / 3, kx = k % 3;
            float acc = 0.f;
            #pragma unroll
            for (int s = 0; s < 3; s++) {
                const float* gp = &g_s[((8 * ky + r) * 24 + 8 * kx + s) * 9];
                const float* wp = &cw_s[((r * 3 + s) * 9) * 9 + o];
                #pragma unroll
                for (int ii = 0; ii < 9; ii++)
                    acc += gp[ii] * wp[ii * 9];
            }
            part_s[r * 81 + k * 9 + o] = acc;
        }
        asm volatile("bar.sync 1, 256;" ::: "memory");
        if (tid < 81)
            c_s[tid] = cb_s[tid % 9] + part_s[tid] + part_s[81 + tid] + part_s[162 + tid];
        asm volatile("bar.sync 1, 256;" ::: "memory");
        if (tid < 9) {
            const int o = tid;
            float ss = 0.f;
            #pragma unroll
            for (int k = 0; k < 9; k++) { const float v = c_s[k * 9 + o]; ss += v * v; }
            const float scale = 1.0f / fmaxf(sqrtf(ss), 1.0f);
            #pragma unroll
            for (int k = 0; k < 9; k++) w1_s[k * 9 + o] = c_s[k * 9 + o] * scale;
        }
    } else if (tid < 544) {
        // warps 8-16: patch mean -> dense -> W2 clip-by-norm (paired layout)
        {
            const int f    = (tid - 256) >> 5;
            const int lane = tid & 31;
            float s = 0.f;
            #pragma unroll
            for (int p = 0; p < 18; p++)
                s += g_s[(lane + 32 * p) * 9 + f];   // lane stride 9 -> conflict-free
            #pragma unroll
            for (int off = 16; off > 0; off >>= 1)
                s += __shfl_down_sync(0xffffffffu, s, off);
            if (lane == 0) gap_s[f] = s * (1.0f / 576.0f);
        }
        asm volatile("bar.sync 2, 288;" ::: "memory");
        if (tid < 337) {
            const int j = tid - 256;                 // 81 threads
            float acc = db_s[j];
            #pragma unroll
            for (int ii = 0; ii < 9; ii++)
                acc += gap_s[ii] * dw_s[ii * 81 + j];
            dvec_s[j] = acc;
        }
        asm volatile("bar.sync 2, 288;" ::: "memory");
        if (tid < 265) {
            const int o = tid - 256;                 // 9 threads
            float ss = 0.f;
            #pragma unroll
            for (int ii = 0; ii < 9; ii++) { const float v = dvec_s[ii * 9 + o]; ss += v * v; }
            const float scale = 1.0f / fmaxf(sqrtf(ss), 1.0f);
            #pragma unroll
            for (int ii = 0; ii < 9; ii++) w2p_s[ii * 10 + o] = dvec_s[ii * 9 + o] * scale;
        }
    }
    __syncthreads();

    // ---- Phase 5a: per-channel depthwise 3x3 from pixel-major tile ----
    //      thread = (channel f, 3x3 pixel block); 25 scalar LDS, conflict-free.
    {
        const int f   = tid >> 6;            // fixed channel per warp
        const int blk = tid & 63;
        const int br  = blk >> 3;
        const int bc  = blk & 7;
        // window rows: slots 3br..3br+4 (pixel rows 3br-1..3br+3)
        const float* dbase = d_s + f + 744 * br;         // 248*3 = 744
        const int q0 = 27 * bc - 9;                      // col 3bc-1 (interior offset)
        const float* pA = dbase + ((bc == 0) ? 225 : q0);// col c=0 (left halo wraps)
        const float* pB = dbase + q0;                    // cols c=1..4 via +9..+36

        float w1f[9];
        #pragma unroll
        for (int k = 0; k < 9; k++) w1f[k] = w1_s[k * 9 + f];  // warp-broadcast

        float win[15];                        // rolling 3-row x 5-col window
        #pragma unroll
        for (int r = 0; r < 3; r++) {
            win[r * 5 + 0] = pA[DROWP * r];
            #pragma unroll
            for (int c = 1; c < 5; c++)
                win[r * 5 + c] = pB[DROWP * r + 9 * c];
        }

        #pragma unroll
        for (int rp = 0; rp < 3; rp++) {
            #pragma unroll
            for (int cp = 0; cp < 3; cp++) {
                float acc = 0.f;
                #pragma unroll
                for (int dy = 0; dy < 3; dy++)
                    #pragma unroll
                    for (int dx = 0; dx < 3; dx++)
                        acc += w1f[dy * 3 + dx] * win[dy * 5 + cp + dx];
                const int pix = (3 * br + rp) * 24 + 3 * bc + cp;
                g_s[pix * 9 + f] = acc;       // banks (8br+27bc)%32: conflict-free
            }
            if (rp < 2) {
                #pragma unroll
                for (int i = 0; i < 10; i++) win[i] = win[i + 5];
                win[10] = pA[DROWP * (rp + 3)];
                #pragma unroll
                for (int c = 1; c < 5; c++)
                    win[10 + c] = pB[DROWP * (rp + 3) + 9 * c];
            }
        }
    }
    __syncthreads();

    // ---- Phase 5b: 9x9 channel mix, packed f32x2, 2 pixels/thread ----
    //      288 threads handle pixels (t, t+288); each w2 LDS.64 feeds 2 FFMA2s.
    //      dc loads/stores stride 9 at t and t+288 (2592%32==0): conflict-free.
    if (tid < 288) {
        const float* dca = &g_s[tid * 9];
        const float* dcb = &g_s[(tid + 288) * 9];

        uint64_t acc_a[5], acc_b[5];
        #pragma unroll
        for (int j = 0; j < 5; j++) { acc_a[j] = 0ull; acc_b[j] = 0ull; }

        #pragma unroll
        for (int ii = 0; ii < 9; ii++) {
            uint64_t sa, sb;
            const uint32_t xa = __float_as_uint(dca[ii]);
            const uint32_t xb = __float_as_uint(dcb[ii]);
            asm("mov.b64 %0, {%1, %1};" : "=l"(sa) : "r"(xa));
            asm("mov.b64 %0, {%1, %1};" : "=l"(sb) : "r"(xb));
            const uint64_t* w2row = reinterpret_cast<const uint64_t*>(&w2p_s[ii * 10]);
            #pragma unroll
            for (int j = 0; j < 5; j++) {
                const uint64_t w2v = w2row[j];       // LDS.64, warp-uniform broadcast
                FMA_F32X2(acc_a[j], sa, w2v, acc_a[j]);
                FMA_F32X2(acc_b[j], sb, w2v, acc_b[j]);
            }
        }

        float* sta = &d_s[tid * 9];                  // d_s is dead; reuse as staging
        float* stb = &d_s[(tid + 288) * 9];
        #pragma unroll
        for (int j = 0; j < 4; j++) {
            sta[2 * j]     = __uint_as_float((uint32_t)acc_a[j]);
            sta[2 * j + 1] = __uint_as_float((uint32_t)(acc_a[j] >> 32));
            stb[2 * j]     = __uint_as_float((uint32_t)acc_b[j]);
            stb[2 * j + 1] = __uint_as_float((uint32_t)(acc_b[j] >> 32));
        }
        sta[8] = __uint_as_float((uint32_t)acc_a[4]);
        stb[8] = __uint_as_float((uint32_t)acc_b[4]);
    }
    __syncthreads();

    // ---- Phase 6: coalesced float4 store of the whole patch ----
    const float4* src = reinterpret_cast<const float4*>(d_s);
    float4* dst = reinterpret_cast<float4*>(out + (size_t)n * 5184);
    #pragma unroll 3
    for (int idx = tid; idx < 1296; idx += THREADS)
        dst[idx] = src[idx];
}

extern "C" void kernel_launch(void* const* d_in, const int* in_sizes, int n_in,
                              void* d_out, int out_size) {
    const float* guidance = (const float*)d_in[0];
    const float* depth    = (const float*)d_in[1];
    const float* conv_w   = (const float*)d_in[2];
    const float* conv_b   = (const float*)d_in[3];
    const float* dense_w  = (const float*)d_in[4];
    const float* dense_b  = (const float*)d_in[5];
    float* out = (float*)d_out;

    guided_conv_kernel<<<4096, THREADS>>>(guidance, depth, conv_w, conv_b,
                                          dense_w, dense_b, out);
}

// round 9
// speedup vs baseline: 1.4375x; 1.1122x over previous
#include <cuda_runtime.h>
#include <cstdint>

// Guided_Conv: 4096 independent 24x24x9 patches.
// patch n = b*256 + i*16 + j  (b=batch, i=patch-row, j=patch-col)
//   input  pixel (pr,pc,f): guidance/depth[ ((b*384 + i*24+pr)*384 + j*24+pc)*9 + f ]
//   output pixel (pr,pc,f): out[ n*5184 + (pr*24+pc)*9 + f ]   (contiguous block per patch)

#define NPIX   576
#define THREADS 576

// Padded pixel-major depth tile with zero halo (see R8):
//   row slot rp = pixel_row+1 in [0,25], row stride DROWP=248 floats (992 B).
//   interior qq in [0,23] at 9*qq; right halo at 216; left halo wrapped to 225.
// 248*3 == 8 (mod 32) -> depthwise-load banks (8*br+27*bc)%32 all distinct.
#define DROWP 248
#define DTILE_FLOATS (DROWP * 26)   // 6448 floats; also >= 5184 for output staging

#define FMA_F32X2(d, a, b, c) \
    asm("fma.rn.f32x2 %0, %1, %2, %3;" : "=l"(d) : "l"(a), "l"(b), "l"(c))

__device__ __forceinline__ uint32_t s2u(const void* p) {
    uint32_t a;
    asm("{ .reg .u64 t; cvta.to.shared.u64 t, %1; cvt.u32.u64 %0, t; }"
        : "=r"(a) : "l"(p));
    return a;
}

__global__ __launch_bounds__(THREADS, 3)
void guided_conv_kernel(const float* __restrict__ guidance,
                        const float* __restrict__ depth,
                        const float* __restrict__ conv_w,   // (3,3,9,9)
                        const float* __restrict__ conv_b,   // (9,)
                        const float* __restrict__ dense_w,  // (9,81)
                        const float* __restrict__ dense_b,  // (81,)
                        float* __restrict__ out)
{
    __shared__ __align__(16) float g_s[NPIX * 9];          // guidance patch -> dc buffer
    __shared__ __align__(16) float d_s[DTILE_FLOATS];      // depth tile -> output staging
    __shared__ float cw_s[729];
    __shared__ float dw_s[729];
    __shared__ float cb_s[9];
    __shared__ float db_s[81];
    __shared__ float c_s[81];                              // conv out [k][o]
    __shared__ float part_s[243];                          // conv partials [r][k*9+o]
    __shared__ float gap_s[9];
    __shared__ float dvec_s[81];                           // dense out [i][o]
    __shared__ float w1_s[81];                             // depthwise kernel [k][f]
    __shared__ __align__(8) float w2p_s[90];               // mix, padded pairs [ii][10]
    __shared__ __align__(8) uint64_t mbar;

    const int n   = blockIdx.x;
    const int b   = n >> 8;
    const int pi  = (n >> 4) & 15;
    const int pj  = n & 15;
    const int tid = threadIdx.x;

    const uint32_t mbar_a = s2u(&mbar);
    const uint32_t gs_a   = s2u(g_s);
    const uint32_t ds_a   = s2u(d_s);

    // ---- Phase 1: bulk-copy input tiles (TMA pipe), weights + halo on LSU ----
    if (tid == 0)
        asm volatile("mbarrier.init.shared.b64 [%0], 1;" :: "r"(mbar_a) : "memory");
    __syncthreads();

    if (tid == 0) {
        asm volatile("mbarrier.arrive.expect_tx.shared.b64 _, [%0], %1;"
                     :: "r"(mbar_a), "r"(41472u) : "memory");
        const long long base_f = ((long long)(b * 384 + pi * 24) * 384 + pj * 24) * 9;
        const char* gsrc = reinterpret_cast<const char*>(guidance + base_f);
        const char* dsrc = reinterpret_cast<const char*>(depth + base_f);
        #pragma unroll 4
        for (int r = 0; r < 24; r++) {
            // rows: 864 B each, src stride 13824 B, all 16B-aligned
            asm volatile(
                "cp.async.bulk.shared::cta.global.mbarrier::complete_tx::bytes "
                "[%0], [%1], %2, [%3];"
                :: "r"(gs_a + 864u * r), "l"(gsrc + 13824ll * r), "r"(864u), "r"(mbar_a)
                : "memory");
            asm volatile(
                "cp.async.bulk.shared::cta.global.mbarrier::complete_tx::bytes "
                "[%0], [%1], %2, [%3];"
                :: "r"(ds_a + 992u * (r + 1)), "l"(dsrc + 13824ll * r), "r"(864u), "r"(mbar_a)
                : "memory");
        }
    } else {
        // halo zero: rows 0 & 25 (234 floats each), cols 216..233 of rows 1..24
        for (int h = tid - 32; h < 900; h += 544) {
            if (h >= 0) {
                int addr;
                if (h < 234)      addr = h;
                else if (h < 468) addr = 6200 + (h - 234);
                else {
                    const int z = h - 468;
                    addr = DROWP * (z / 18 + 1) + 216 + (z % 18);
                }
                d_s[addr] = 0.f;
            }
        }
        for (int idx = tid - 32; idx < 729; idx += 544) {
            if (idx >= 0) {
                cw_s[idx] = conv_w[idx];
                dw_s[idx] = dense_w[idx];
            }
        }
        if (tid >= 64 && tid < 145) db_s[tid - 64] = dense_b[tid - 64];
        if (tid >= 160 && tid < 169) cb_s[tid - 160] = conv_b[tid - 160];
        if (tid >= 192 && tid < 201) w2p_s[(tid - 192) * 10 + 9] = 0.f;
    }
    __syncthreads();           // weights/halo visible CTA-wide

    // wait for both input tiles (parity 0; mbar re-initialized every launch)
    asm volatile(
        "{\n\t.reg .pred P;\n\t"
        "LW_%=:\n\t"
        "mbarrier.try_wait.parity.acquire.cta.shared::cta.b64 P, [%0], %1;\n\t"
        "@!P bra LW_%=;\n\t}"
        :: "r"(mbar_a), "r"(0) : "memory");

    // ---- Phase 2: two independent weight chains on disjoint warp groups ----
    if (tid < 256) {
        // warps 0-7: conv partials (243 thr) -> sum -> W1 clip-by-norm
        if (tid < 243) {
            const int o  = tid % 9;
            const int k  = (tid / 9) % 9;
            const int r  = tid / 81;
            const int ky = k / 3, kx = k % 3;
            float acc = 0.f;
            #pragma unroll
            for (int s = 0; s < 3; s++) {
                const float* gp = &g_s[((8 * ky + r) * 24 + 8 * kx + s) * 9];
                const float* wp = &cw_s[((r * 3 + s) * 9) * 9 + o];
                #pragma unroll
                for (int ii = 0; ii < 9; ii++)
                    acc += gp[ii] * wp[ii * 9];
            }
            part_s[r * 81 + k * 9 + o] = acc;
        }
        asm volatile("bar.sync 1, 256;" ::: "memory");
        if (tid < 81)
            c_s[tid] = cb_s[tid % 9] + part_s[tid] + part_s[81 + tid] + part_s[162 + tid];
        asm volatile("bar.sync 1, 256;" ::: "memory");
        if (tid < 9) {
            const int o = tid;
            float ss = 0.f;
            #pragma unroll
            for (int k = 0; k < 9; k++) { const float v = c_s[k * 9 + o]; ss += v * v; }
            const float scale = 1.0f / fmaxf(sqrtf(ss), 1.0f);
            #pragma unroll
            for (int k = 0; k < 9; k++) w1_s[k * 9 + o] = c_s[k * 9 + o] * scale;
        }
    } else if (tid < 544) {
        // warps 8-16: patch mean -> dense -> W2 clip-by-norm (paired layout)
        {
            const int f    = (tid - 256) >> 5;
            const int lane = tid & 31;
            float s = 0.f;
            #pragma unroll
            for (int p = 0; p < 18; p++)
                s += g_s[(lane + 32 * p) * 9 + f];   // lane stride 9 -> conflict-free
            #pragma unroll
            for (int off = 16; off > 0; off >>= 1)
                s += __shfl_down_sync(0xffffffffu, s, off);
            if (lane == 0) gap_s[f] = s * (1.0f / 576.0f);
        }
        asm volatile("bar.sync 2, 288;" ::: "memory");
        if (tid < 337) {
            const int j = tid - 256;
            float acc = db_s[j];
            #pragma unroll
            for (int ii = 0; ii < 9; ii++)
                acc += gap_s[ii] * dw_s[ii * 81 + j];
            dvec_s[j] = acc;
        }
        asm volatile("bar.sync 2, 288;" ::: "memory");
        if (tid < 265) {
            const int o = tid - 256;
            float ss = 0.f;
            #pragma unroll
            for (int ii = 0; ii < 9; ii++) { const float v = dvec_s[ii * 9 + o]; ss += v * v; }
            const float scale = 1.0f / fmaxf(sqrtf(ss), 1.0f);
            #pragma unroll
            for (int ii = 0; ii < 9; ii++) w2p_s[ii * 10 + o] = dvec_s[ii * 9 + o] * scale;
        }
    }
    __syncthreads();

    // ---- Phase 5a: per-channel depthwise 3x3 from pixel-major tile ----
    {
        const int f   = tid >> 6;
        const int blk = tid & 63;
        const int br  = blk >> 3;
        const int bc  = blk & 7;
        const float* dbase = d_s + f + 744 * br;          // 248*3 = 744
        const int q0 = 27 * bc - 9;                       // col 3bc-1 interior offset
        const float* pA = dbase + ((bc == 0) ? 225 : q0); // left col (halo wraps)
        const float* pB = dbase + q0;

        float w1f[9];
        #pragma unroll
        for (int k = 0; k < 9; k++) w1f[k] = w1_s[k * 9 + f];

        float win[15];
        #pragma unroll
        for (int r = 0; r < 3; r++) {
            win[r * 5 + 0] = pA[DROWP * r];
            #pragma unroll
            for (int c = 1; c < 5; c++)
                win[r * 5 + c] = pB[DROWP * r + 9 * c];
        }

        #pragma unroll
        for (int rp = 0; rp < 3; rp++) {
            #pragma unroll
            for (int cp = 0; cp < 3; cp++) {
                float acc = 0.f;
                #pragma unroll
                for (int dy = 0; dy < 3; dy++)
                    #pragma unroll
                    for (int dx = 0; dx < 3; dx++)
                        acc += w1f[dy * 3 + dx] * win[dy * 5 + cp + dx];
                const int pix = (3 * br + rp) * 24 + 3 * bc + cp;
                g_s[pix * 9 + f] = acc;                   // conflict-free
            }
            if (rp < 2) {
                #pragma unroll
                for (int i = 0; i < 10; i++) win[i] = win[i + 5];
                win[10] = pA[DROWP * (rp + 3)];
                #pragma unroll
                for (int c = 1; c < 5; c++)
                    win[10 + c] = pB[DROWP * (rp + 3) + 9 * c];
            }
        }
    }
    __syncthreads();

    // ---- Phase 5b: 9x9 channel mix, packed f32x2, 2 pixels/thread ----
    if (tid < 288) {
        const float* dca = &g_s[tid * 9];
        const float* dcb = &g_s[(tid + 288) * 9];

        uint64_t acc_a[5], acc_b[5];
        #pragma unroll
        for (int j = 0; j < 5; j++) { acc_a[j] = 0ull; acc_b[j] = 0ull; }

        #pragma unroll
        for (int ii = 0; ii < 9; ii++) {
            uint64_t sa, sb;
            const uint32_t xa = __float_as_uint(dca[ii]);
            const uint32_t xb = __float_as_uint(dcb[ii]);
            asm("mov.b64 %0, {%1, %1};" : "=l"(sa) : "r"(xa));
            asm("mov.b64 %0, {%1, %1};" : "=l"(sb) : "r"(xb));
            const uint64_t* w2row = reinterpret_cast<const uint64_t*>(&w2p_s[ii * 10]);
            #pragma unroll
            for (int j = 0; j < 5; j++) {
                const uint64_t w2v = w2row[j];            // LDS.64 broadcast
                FMA_F32X2(acc_a[j], sa, w2v, acc_a[j]);
                FMA_F32X2(acc_b[j], sb, w2v, acc_b[j]);
            }
        }

        float* sta = &d_s[tid * 9];                       // d_s dead; reuse as staging
        float* stb = &d_s[(tid + 288) * 9];
        #pragma unroll
        for (int j = 0; j < 4; j++) {
            sta[2 * j]     = __uint_as_float((uint32_t)acc_a[j]);
            sta[2 * j + 1] = __uint_as_float((uint32_t)(acc_a[j] >> 32));
            stb[2 * j]     = __uint_as_float((uint32_t)acc_b[j]);
            stb[2 * j + 1] = __uint_as_float((uint32_t)(acc_b[j] >> 32));
        }
        sta[8] = __uint_as_float((uint32_t)acc_a[4]);
        stb[8] = __uint_as_float((uint32_t)acc_b[4]);
    }
    __syncthreads();

    // ---- Phase 6: single bulk store of the whole patch (20736 B) ----
    if (tid == 0) {
        asm volatile("fence.proxy.async;" ::: "memory");
        asm volatile(
            "cp.async.bulk.global.shared::cta.bulk_group [%0], [%1], %2;"
            :: "l"(out + (size_t)n * 5184), "r"(ds_a), "r"(20736u) : "memory");
        asm volatile("cp.async.bulk.commit_group;" ::: "memory");
        asm volatile("cp.async.bulk.wait_group 0;" ::: "memory");
    }
}

extern "C" void kernel_launch(void* const* d_in, const int* in_sizes, int n_in,
                              void* d_out, int out_size) {
    const float* guidance = (const float*)d_in[0];
    const float* depth    = (const float*)d_in[1];
    const float* conv_w   = (const float*)d_in[2];
    const float* conv_b   = (const float*)d_in[3];
    const float* dense_w  = (const float*)d_in[4];
    const float* dense_b  = (const float*)d_in[5];
    float* out = (float*)d_out;

    guided_conv_kernel<<<4096, THREADS>>>(guidance, depth, conv_w, conv_b,
                                          dense_w, dense_b, out);
}

// round 10
// speedup vs baseline: 1.6761x; 1.1660x over previous
#include <cuda_runtime.h>
#include <cstdint>

// Guided_Conv: 4096 independent 24x24x9 patches, persistent-CTA pipelined.
// patch n = b*256 + i*16 + j; output block at out + n*5184 (contiguous).

#define THREADS 576
#define GRID    444            // 148 SMs x 3 CTAs: exactly one wave
#define NPATCH  4096

// Padded pixel-major depth tile with zero halo (row stride 248 floats = 992 B).
// 248*3 == 8 (mod 32) -> depthwise-load banks (8*br+27*bc)%32 all distinct.
#define DROWP 248
#define DTILE_FLOATS (DROWP * 26)

#define FMA_F32X2(d, a, b, c) \
    asm("fma.rn.f32x2 %0, %1, %2, %3;" : "=l"(d) : "l"(a), "l"(b), "l"(c))

__device__ __forceinline__ uint32_t s2u(const void* p) {
    uint32_t a;
    asm("{ .reg .u64 t; cvta.to.shared.u64 t, %1; cvt.u32.u64 %0, t; }"
        : "=r"(a) : "l"(p));
    return a;
}

__device__ __forceinline__ void mbar_wait(uint32_t addr, uint32_t parity) {
    asm volatile(
        "{\n\t.reg .pred P;\n\t"
        "LW_%=:\n\t"
        "mbarrier.try_wait.parity.acquire.cta.shared::cta.b64 P, [%0], %1;\n\t"
        "@!P bra LW_%=;\n\t}"
        :: "r"(addr), "r"(parity) : "memory");
}

// Issue one 24-row tile load (20736 B) into smem via bulk-async, tx on mbar.
__device__ __forceinline__ void issue_tile(uint32_t mbar_a, uint32_t dst,
                                           uint32_t dst_stride, const char* src) {
    asm volatile("mbarrier.arrive.expect_tx.shared.b64 _, [%0], %1;"
                 :: "r"(mbar_a), "r"(20736u) : "memory");
    #pragma unroll 4
    for (int r = 0; r < 24; r++) {
        asm volatile(
            "cp.async.bulk.shared::cta.global.mbarrier::complete_tx::bytes "
            "[%0], [%1], %2, [%3];"
            :: "r"(dst + dst_stride * r), "l"(src + 13824ll * r), "r"(864u), "r"(mbar_a)
            : "memory");
    }
}

__device__ __forceinline__ const char* patch_src(const float* base, int n) {
    const int b  = n >> 8;
    const int pi = (n >> 4) & 15;
    const int pj = n & 15;
    const long long f = ((long long)(b * 384 + pi * 24) * 384 + pj * 24) * 9;
    return reinterpret_cast<const char*>(base + f);
}

__global__ __launch_bounds__(THREADS, 3)
void guided_conv_kernel(const float* __restrict__ guidance,
                        const float* __restrict__ depth,
                        const float* __restrict__ conv_w,   // (3,3,9,9)
                        const float* __restrict__ conv_b,   // (9,)
                        const float* __restrict__ dense_w,  // (9,81)
                        const float* __restrict__ dense_b,  // (81,)
                        float* __restrict__ out)
{
    __shared__ __align__(16) float g_s[2 * 5184];      // guidance -> dc -> output (per buf)
    __shared__ __align__(16) float d_s[DTILE_FLOATS];  // depth input tile (halo, input-only)
    __shared__ float cw_s[729];
    __shared__ float dw_s[729];
    __shared__ float cb_s[9];
    __shared__ float db_s[81];
    __shared__ float c_s[81];
    __shared__ float part_s[243];
    __shared__ float gap_s[9];
    __shared__ float dvec_s[81];
    __shared__ float w1_s[81];
    __shared__ __align__(8) float w2p_s[90];
    __shared__ __align__(8) uint64_t mbars[3];         // g0, g1, d

    const int tid = threadIdx.x;
    const uint32_t mbg0 = s2u(&mbars[0]);
    const uint32_t mbg1 = s2u(&mbars[1]);
    const uint32_t mbd  = s2u(&mbars[2]);
    const uint32_t gs_a = s2u(g_s);
    const uint32_t ds_a = s2u(d_s);

    // ================= Prologue (once per CTA) =================
    if (tid == 0) {
        asm volatile("mbarrier.init.shared.b64 [%0], 1;" :: "r"(mbg0) : "memory");
        asm volatile("mbarrier.init.shared.b64 [%0], 1;" :: "r"(mbg1) : "memory");
        asm volatile("mbarrier.init.shared.b64 [%0], 1;" :: "r"(mbd)  : "memory");
    }
    // zero all depth-halo cells (900 floats): rows 0 & 25 + col slots 216..233 of rows 1..24
    for (int h = tid; h < 900; h += THREADS) {
        int addr;
        if (h < 234)      addr = h;
        else if (h < 468) addr = 6200 + (h - 234);
        else {
            const int z = h - 468;
            addr = DROWP * (z / 18 + 1) + 216 + (z % 18);
        }
        d_s[addr] = 0.f;
    }
    // weights (once)
    for (int idx = tid; idx < 729; idx += THREADS) {
        cw_s[idx] = conv_w[idx];
        dw_s[idx] = dense_w[idx];
    }
    if (tid < 81) db_s[tid] = dense_b[tid];
    if (tid >= 96 && tid < 105) cb_s[tid - 96] = conv_b[tid - 96];
    if (tid >= 112 && tid < 121) w2p_s[(tid - 112) * 10 + 9] = 0.f;
    __syncthreads();

    const int i0 = blockIdx.x;
    if (tid == 544) {
        issue_tile(mbg0, gs_a, 864u, patch_src(guidance, i0));       // g(patch0) -> g[0]
        issue_tile(mbd,  ds_a + 992u, 992u, patch_src(depth, i0));   // d(patch0)
    }

    // ================= Pipelined main loop =================
    int it = 0;
    for (int i = i0; i < NPATCH; i += GRID, ++it) {
        const int p = it & 1;
        float* gc = g_s + p * 5184;

        // -- step 1 (warp 17): after prior store drains, prefetch NEXT guidance --
        if (tid == 544) {
            asm volatile("cp.async.bulk.wait_group 0;" ::: "memory");
            if (i + GRID < NPATCH)
                issue_tile(p ? mbg0 : mbg1, gs_a + (1 - p) * 20736u, 864u,
                           patch_src(guidance, i + GRID));
        }

        // -- step 2: wait current guidance (parity closed-form) --
        mbar_wait(p ? mbg1 : mbg0, (uint32_t)((it >> 1) & 1));

        // -- phase 2: two independent weight chains on disjoint warp groups --
        if (tid < 256) {
            if (tid < 243) {
                const int o  = tid % 9;
                const int k  = (tid / 9) % 9;
                const int r  = tid / 81;
                const int ky = k / 3, kx = k % 3;
                float acc = 0.f;
                #pragma unroll
                for (int s = 0; s < 3; s++) {
                    const float* gp = &gc[((8 * ky + r) * 24 + 8 * kx + s) * 9];
                    const float* wp = &cw_s[((r * 3 + s) * 9) * 9 + o];
                    #pragma unroll
                    for (int ii = 0; ii < 9; ii++)
                        acc += gp[ii] * wp[ii * 9];
                }
                part_s[r * 81 + k * 9 + o] = acc;
            }
            asm volatile("bar.sync 1, 256;" ::: "memory");
            if (tid < 81)
                c_s[tid] = cb_s[tid % 9] + part_s[tid] + part_s[81 + tid] + part_s[162 + tid];
            asm volatile("bar.sync 1, 256;" ::: "memory");
            if (tid < 9) {
                const int o = tid;
                float ss = 0.f;
                #pragma unroll
                for (int k = 0; k < 9; k++) { const float v = c_s[k * 9 + o]; ss += v * v; }
                const float scale = 1.0f / fmaxf(sqrtf(ss), 1.0f);
                #pragma unroll
                for (int k = 0; k < 9; k++) w1_s[k * 9 + o] = c_s[k * 9 + o] * scale;
            }
        } else if (tid < 544) {
            {
                const int f    = (tid - 256) >> 5;
                const int lane = tid & 31;
                float s = 0.f;
                #pragma unroll
                for (int pp = 0; pp < 18; pp++)
                    s += gc[(lane + 32 * pp) * 9 + f];   // stride 9 -> conflict-free
                #pragma unroll
                for (int off = 16; off > 0; off >>= 1)
                    s += __shfl_down_sync(0xffffffffu, s, off);
                if (lane == 0) gap_s[f] = s * (1.0f / 576.0f);
            }
            asm volatile("bar.sync 2, 288;" ::: "memory");
            if (tid < 337) {
                const int j = tid - 256;
                float acc = db_s[j];
                #pragma unroll
                for (int ii = 0; ii < 9; ii++)
                    acc += gap_s[ii] * dw_s[ii * 81 + j];
                dvec_s[j] = acc;
            }
            asm volatile("bar.sync 2, 288;" ::: "memory");
            if (tid < 265) {
                const int o = tid - 256;
                float ss = 0.f;
                #pragma unroll
                for (int ii = 0; ii < 9; ii++) { const float v = dvec_s[ii * 9 + o]; ss += v * v; }
                const float scale = 1.0f / fmaxf(sqrtf(ss), 1.0f);
                #pragma unroll
                for (int ii = 0; ii < 9; ii++) w2p_s[ii * 10 + o] = dvec_s[ii * 9 + o] * scale;
            }
        }
        __syncthreads();

        // -- step 4: wait current depth input --
        mbar_wait(mbd, (uint32_t)(it & 1));

        // -- phase 5a: per-channel depthwise 3x3; dc overwrites gc (guidance dead) --
        {
            const int f   = tid >> 6;
            const int blk = tid & 63;
            const int br  = blk >> 3;
            const int bc  = blk & 7;
            const float* dbase = d_s + f + 744 * br;          // 248*3
            const int q0 = 27 * bc - 9;
            const float* pA = dbase + ((bc == 0) ? 225 : q0); // left col (halo wraps)
            const float* pB = dbase + q0;

            float w1f[9];
            #pragma unroll
            for (int k = 0; k < 9; k++) w1f[k] = w1_s[k * 9 + f];

            float win[15];
            #pragma unroll
            for (int r = 0; r < 3; r++) {
                win[r * 5 + 0] = pA[DROWP * r];
                #pragma unroll
                for (int c = 1; c < 5; c++)
                    win[r * 5 + c] = pB[DROWP * r + 9 * c];
            }

            #pragma unroll
            for (int rp = 0; rp < 3; rp++) {
                #pragma unroll
                for (int cp = 0; cp < 3; cp++) {
                    float acc = 0.f;
                    #pragma unroll
                    for (int dy = 0; dy < 3; dy++)
                        #pragma unroll
                        for (int dx = 0; dx < 3; dx++)
                            acc += w1f[dy * 3 + dx] * win[dy * 5 + cp + dx];
                    const int pix = (3 * br + rp) * 24 + 3 * bc + cp;
                    gc[pix * 9 + f] = acc;                    // conflict-free
                }
                if (rp < 2) {
                    #pragma unroll
                    for (int ii = 0; ii < 10; ii++) win[ii] = win[ii + 5];
                    win[10] = pA[DROWP * (rp + 3)];
                    #pragma unroll
                    for (int c = 1; c < 5; c++)
                        win[10 + c] = pB[DROWP * (rp + 3) + 9 * c];
                }
            }
        }
        __syncthreads();

        // -- step 6 (warp 17): depth consumed -> prefetch NEXT depth (no wait needed) --
        if (tid == 544 && i + GRID < NPATCH)
            issue_tile(mbd, ds_a + 992u, 992u, patch_src(depth, i + GRID));

        // -- phase 5b: 9x9 channel mix IN-PLACE in gc (packed f32x2, 2 px/thread) --
        if (tid < 288) {
            float* dca = &gc[tid * 9];
            float* dcb = &gc[(tid + 288) * 9];

            uint64_t acc_a[5], acc_b[5];
            #pragma unroll
            for (int j = 0; j < 5; j++) { acc_a[j] = 0ull; acc_b[j] = 0ull; }

            float va[9], vb[9];
            #pragma unroll
            for (int ii = 0; ii < 9; ii++) { va[ii] = dca[ii]; vb[ii] = dcb[ii]; }

            #pragma unroll
            for (int ii = 0; ii < 9; ii++) {
                uint64_t sa, sb;
                const uint32_t xa = __float_as_uint(va[ii]);
                const uint32_t xb = __float_as_uint(vb[ii]);
                asm("mov.b64 %0, {%1, %1};" : "=l"(sa) : "r"(xa));
                asm("mov.b64 %0, {%1, %1};" : "=l"(sb) : "r"(xb));
                const uint64_t* w2row = reinterpret_cast<const uint64_t*>(&w2p_s[ii * 10]);
                #pragma unroll
                for (int j = 0; j < 5; j++) {
                    const uint64_t w2v = w2row[j];            // LDS.64 broadcast
                    FMA_F32X2(acc_a[j], sa, w2v, acc_a[j]);
                    FMA_F32X2(acc_b[j], sb, w2v, acc_b[j]);
                }
            }

            #pragma unroll
            for (int j = 0; j < 4; j++) {
                dca[2 * j]     = __uint_as_float((uint32_t)acc_a[j]);
                dca[2 * j + 1] = __uint_as_float((uint32_t)(acc_a[j] >> 32));
                dcb[2 * j]     = __uint_as_float((uint32_t)acc_b[j]);
                dcb[2 * j + 1] = __uint_as_float((uint32_t)(acc_b[j] >> 32));
            }
            dca[8] = __uint_as_float((uint32_t)acc_a[4]);
            dcb[8] = __uint_as_float((uint32_t)acc_b[4]);
        }
        __syncthreads();

        // -- step 8 (warp 17): bulk-store the patch from gc; wait deferred to step 1 --
        if (tid == 544) {
            asm volatile("fence.proxy.async;" ::: "memory");
            asm volatile(
                "cp.async.bulk.global.shared::cta.bulk_group [%0], [%1], %2;"
                :: "l"(out + (size_t)i * 5184), "r"(gs_a + p * 20736u), "r"(20736u)
                : "memory");
            asm volatile("cp.async.bulk.commit_group;" ::: "memory");
        }
    }

    // drain the final output store before CTA retirement
    if (tid == 544)
        asm volatile("cp.async.bulk.wait_group 0;" ::: "memory");
}

extern "C" void kernel_launch(void* const* d_in, const int* in_sizes, int n_in,
                              void* d_out, int out_size) {
    const float* guidance = (const float*)d_in[0];
    const float* depth    = (const float*)d_in[1];
    const float* conv_w   = (const float*)d_in[2];
    const float* conv_b   = (const float*)d_in[3];
    const float* dense_w  = (const float*)d_in[4];
    const float* dense_b  = (const float*)d_in[5];
    float* out = (float*)d_out;

    guided_conv_kernel<<<GRID, THREADS>>>(guidance, depth, conv_w, conv_b,
                                          dense_w, dense_b, out);
}